// round 7
// baseline (speedup 1.0000x reference)
#include <cuda_runtime.h>
#include <cuda_bf16.h>
#include <cstdint>

#define HD 150
#define HP 160
#define GDIM 1000
#define GRIDW 129
#define NCHUNK 17
#define TILE_M 256

typedef unsigned long long ull;

// ---------------- helpers ----------------
__device__ __forceinline__ uint32_t smem_u32(const void* p){
    uint32_t a; asm("{ .reg .u64 t; cvta.to.shared.u64 t, %1; cvt.u32.u64 %0, t; }" : "=r"(a) : "l"(p));
    return a;
}
__device__ __forceinline__ uint32_t mul2(uint32_t a, uint32_t b){
    uint32_t r; asm("mul.bf16x2 %0,%1,%2;" : "=r"(r) : "r"(a), "r"(b)); return r;
}
#define CVTB2(res,a,b) asm("cvt.rn.satfinite.bf16x2.f32 %0, %1, %2;" : "=r"(res) : "f"(b), "f"(a))
#define STS128(r0,r1,r2,r3,addr) asm volatile("st.shared.v4.b32 [%0], {%1,%2,%3,%4};" :: "r"(addr), "r"(r0), "r"(r1), "r"(r2), "r"(r3) : "memory")
#define STS32(addr,v) asm volatile("st.shared.b32 [%0], %1;" :: "r"(addr), "r"(v) : "memory")
#define SWZ(a) ((a) ^ (((a)>>3)&0x70))

#define CPA16(dst,src) asm volatile("cp.async.cg.shared.global [%0], [%1], 16;" :: "r"((uint32_t)(dst)), "l"(src) : "memory")
#define CPC() asm volatile("cp.async.commit_group;" ::: "memory")
#define CPW0() asm volatile("cp.async.wait_group 0;" ::: "memory")
#define CPW1() asm volatile("cp.async.wait_group 1;" ::: "memory")
#define CPW2() asm volatile("cp.async.wait_group 2;" ::: "memory")

#define LDSM4(r0,r1,r2,r3,addr) \
    asm volatile("ldmatrix.sync.aligned.m8n8.x4.shared.b16 {%0,%1,%2,%3}, [%4];" \
        : "=r"(r0),"=r"(r1),"=r"(r2),"=r"(r3) : "r"(addr))
#define LDSM2(r0,r1,addr) \
    asm volatile("ldmatrix.sync.aligned.m8n8.x2.shared.b16 {%0,%1}, [%2];" \
        : "=r"(r0),"=r"(r1) : "r"(addr))

#define MMA(d,a,b) \
    asm volatile("mma.sync.aligned.m16n8k16.row.col.f32.bf16.bf16.f32 " \
        "{%0,%1,%2,%3},{%4,%5,%6,%7},{%8,%9},{%0,%1,%2,%3};" \
        : "+f"((d)[0]),"+f"((d)[1]),"+f"((d)[2]),"+f"((d)[3]) \
        : "r"((a)[0]),"r"((a)[1]),"r"((a)[2]),"r"((a)[3]),"r"((b)[0]),"r"((b)[1]))

// ---------------- scratch ----------------
__device__ uint32_t g_gib[4096 * 512];          // gi as bf16x2, K padded to 1024
__device__ uint32_t g_ABpack[2 * 16 * 5120];    // W1a^T, W1b^T pre-swizzled chunks
__device__ uint32_t g_Bpack[NCHUNK * 5120];     // W1c^T / W1d^T chunks
__device__ uint32_t g_B2pack[3 * 5120];         // W2^T chunks
__device__ float g_A[4096 * HP];
__device__ float g_B[4096 * HP];
__device__ float g_scores[132096];
__device__ int   g_starts[2048];

// ============================================================
// warp MMA consumer, N40: per k16 -> MT LDSM4 (A) + 2 LDSM4 + 1 LDSM2 (B)
// ============================================================
template<int MT>
__device__ __forceinline__ void mma_chunk40(uint32_t Ab, uint32_t Bb, int nk16,
                                            int mrow0, int nrow0, int lane,
                                            float (&acc)[MT][5][4])
{
    const int a_row = mrow0 + ((lane>>3)&1)*8 + (lane&7);
    const int a_cb  = (lane>>4)*16;
    const int b_row = nrow0 + ((lane>>4)&1)*8 + (lane&7);
    const int b_cb  = ((lane>>3)&1)*16;
    const int b2_row = nrow0 + 32 + (lane&7);
    const int b2_cb  = ((lane>>3)&1)*16;
    #pragma unroll
    for (int k16 = 0; k16 < nk16; k16++) {
        const int kb = k16 * 32;
        uint32_t b[5][2];
        #pragma unroll
        for (int g = 0; g < 2; g++) {
            uint32_t bd = Bb + SWZ((uint32_t)((b_row + g*16)*128 + kb + b_cb));
            uint32_t r0, r1, r2, r3;
            LDSM4(r0, r1, r2, r3, bd);
            b[2*g][0] = r0; b[2*g][1] = r1; b[2*g+1][0] = r2; b[2*g+1][1] = r3;
        }
        {
            uint32_t bd = Bb + SWZ((uint32_t)(b2_row*128 + kb + b2_cb));
            LDSM2(b[4][0], b[4][1], bd);
        }
        #pragma unroll
        for (int mt = 0; mt < MT; mt++) {
            uint32_t a[4];
            uint32_t ad = Ab + SWZ((uint32_t)((a_row + mt*16)*128 + kb + a_cb));
            LDSM4(a[0], a[1], a[2], a[3], ad);
            #pragma unroll
            for (int nt = 0; nt < 5; nt++)
                MMA(acc[mt][nt], a, b[nt]);
        }
    }
}

// ============================================================
// prep (fused with fill + starts)
// ============================================================
__global__ void k_prep(const float* __restrict__ gi, const float* __restrict__ W1,
                       const float* __restrict__ W2,
                       const int* __restrict__ offs, const int* __restrict__ segs,
                       float* __restrict__ out, int NSPAN, int P, int out_total)
{
    long long idx = (long long)blockIdx.x * 256 + threadIdx.x;
    const long long NG  = (long long)NSPAN * 512;
    const long long AB  = NG + 2 * 16 * 5120;
    const long long BP  = AB + NCHUNK * 5120;
    const long long B2E = BP + 3 * 5120;
    const long long FE  = B2E + out_total;
    const long long SE  = FE + P;
    if (idx < NG) {
        int n = (int)(idx >> 9), kw = (int)(idx & 511);
        int c0 = kw * 2;
        float a = (c0     < GDIM) ? gi[(size_t)n * GDIM + c0]     : 0.f;
        float b = (c0 + 1 < GDIM) ? gi[(size_t)n * GDIM + c0 + 1] : 0.f;
        uint32_t w; CVTB2(w, a, b);
        g_gib[idx] = w;
    } else if (idx < AB) {
        int t = (int)(idx - NG);
        int sel = t / (16 * 5120); int rem = t - sel * 16 * 5120;
        int c = rem / 5120, r = rem % 5120;
        int n = r >> 5, kk = (r & 31) * 2;
        int kg = c * 64 + kk;
        float v0 = 0.f, v1 = 0.f;
        if (n < HD) {
            if (kg     < GDIM) v0 = W1[(size_t)(sel * GDIM + kg)     * HD + n];
            if (kg + 1 < GDIM) v1 = W1[(size_t)(sel * GDIM + kg + 1) * HD + n];
        }
        uint32_t w; CVTB2(w, v0, v1);
        uint32_t off = (uint32_t)(n * 128 + kk * 2);
        g_ABpack[(sel * 16 + c) * 5120 + (SWZ(off) >> 2)] = w;
    } else if (idx < BP) {
        int t = (int)(idx - AB);
        int c = t / 5120, r = t % 5120;
        int n = r >> 5, kk = (r & 31) * 2;
        float v0 = 0.f, v1 = 0.f;
        if (n < HD) {
            if (c < 16) {
                int kg = c * 64 + kk;
                if (kg     < GDIM) v0 = W1[(size_t)(2000 + kg)     * HD + n];
                if (kg + 1 < GDIM) v1 = W1[(size_t)(2001 + kg)     * HD + n];
            } else {
                if (kk     < 60) v0 = W1[(size_t)(3000 + kk)     * HD + n];
                if (kk + 1 < 60) v1 = W1[(size_t)(3001 + kk)     * HD + n];
            }
        }
        uint32_t w; CVTB2(w, v0, v1);
        uint32_t off = (uint32_t)(n * 128 + kk * 2);
        g_Bpack[c * 5120 + (SWZ(off) >> 2)] = w;
    } else if (idx < B2E) {
        int t = (int)(idx - BP);
        int c = t / 5120, r = t % 5120;
        int n = r >> 5, kk = (r & 31) * 2;
        int kg = c * 64 + kk;
        float v0 = 0.f, v1 = 0.f;
        if (n < HD) {
            if (kg     < HD) v0 = W2[(size_t)kg       * HD + n];
            if (kg + 1 < HD) v1 = W2[(size_t)(kg + 1) * HD + n];
        }
        uint32_t w; CVTB2(w, v0, v1);
        uint32_t off = (uint32_t)(n * 128 + kk * 2);
        g_B2pack[c * 5120 + (SWZ(off) >> 2)] = w;
    } else if (idx < FE) {
        long long i = idx - B2E;
        out[i] = (i == 0) ? 1.0f : 1000.0f;
    } else if (idx < SE) {
        int p = (int)(idx - FE);
        if (offs[p] == 0) g_starts[segs[p]] = p;
    }
}

// ============================================================
// k_pre: g_A = gi @ W1a, g_B = gi @ W1b  (unchanged from R6)
// ============================================================
__global__ __launch_bounds__(512) void k_pre()
{
    extern __shared__ char dsm[];
    const int tid = threadIdx.x;
    const int lane = tid & 31;
    const int wid = tid >> 5;
    const int mw = wid & 3, nw = wid >> 2;
    const int n0 = blockIdx.x * 64;
    const int sel = blockIdx.y;

    uint32_t rbase = (smem_u32(dsm) + 1023u) & ~1023u;
    const char* Bsrc = (const char*)(g_ABpack + sel * 16 * 5120);

    float acc[1][5][4];
    #pragma unroll
    for (int j = 0; j < 5; j++)
        #pragma unroll
        for (int k = 0; k < 4; k++) acc[0][j][k] = 0.f;

    auto issue = [&](int c) {
        int s = c & 3;
        uint32_t Ab = rbase + (uint32_t)(s * 8192);
        uint32_t Bb = rbase + 32768u + (uint32_t)(s * 20480);
        {
            int row = tid >> 3, seg = tid & 7;
            const char* src = (const char*)g_gib + ((size_t)(n0 + row) * 2048 + c * 128 + seg * 16);
            CPA16(Ab + SWZ((uint32_t)(row * 128 + seg * 16)), src);
        }
        #pragma unroll
        for (int t = 0; t < 3; t++) {
            int j = tid + t * 512;
            if (j < 1280) CPA16(Bb + (uint32_t)(j * 16), Bsrc + (size_t)c * 20480 + j * 16);
        }
        CPC();
    };

    issue(0); issue(1); issue(2);
    for (int c = 0; c < 16; c++) {
        if (c <= 13) CPW2(); else if (c == 14) CPW1(); else CPW0();
        __syncthreads();
        if (c + 3 < 16) issue(c + 3);
        int s = c & 3;
        mma_chunk40<1>(rbase + (uint32_t)(s * 8192),
                       rbase + 32768u + (uint32_t)(s * 20480),
                       4, mw * 16, nw * 40, lane, acc);
    }

    float* dst = sel ? g_B : g_A;
    #pragma unroll
    for (int half = 0; half < 2; half++) {
        int row = n0 + mw * 16 + (lane >> 2) + half * 8;
        #pragma unroll
        for (int nt = 0; nt < 5; nt++) {
            int cc = nw * 40 + nt * 8 + (lane & 3) * 2;
            *(float2*)(dst + (size_t)row * HP + cc) =
                make_float2(acc[0][nt][half * 2], acc[0][nt][half * 2 + 1]);
        }
    }
}

// ============================================================
// fused pair kernel, M=256 per CTA: layer1 + relu + layer2 + score
// 512 threads; warp grid 4x4: M64 x N40; 3-deep B ring
// ============================================================
__global__ __launch_bounds__(512) void k_fused(
    const float* __restrict__ b1, const float* __restrict__ b2,
    const float* __restrict__ W3, const float* __restrict__ b3,
    const float* __restrict__ ms,
    const float* __restrict__ de, const float* __restrict__ ge, const float* __restrict__ se,
    const int* __restrict__ mi, const int* __restrict__ ai,
    const int* __restrict__ di, const int* __restrict__ gx, const int* __restrict__ si,
    int P)
{
    extern __shared__ char dsm[];
    __shared__ int smi[TILE_M], sai[TILE_M], sdi[TILE_M], sgi[TILE_M], ssi[TILE_M];
    __shared__ __align__(16) float s_b1[HP], s_b2[HP], s_w3[HP];
    __shared__ float sred[TILE_M][4];

    const int tid = threadIdx.x;
    const int lane = tid & 31;
    const int wid = tid >> 5;
    const int mw = wid & 3, nw = wid >> 2;
    const int p0 = blockIdx.x * TILE_M;

    uint32_t rbase = (smem_u32(dsm) + 1023u) & ~1023u;
    // layer1: A bufs 2x32KB [0,65536); B ring 3x20KB [65536,126976)
    // epilogue: H 3x32KB [0,98304); W2 3x20KB [98304,159744)
    const uint32_t Hb  = rbase;
    const uint32_t W2b = rbase + 98304u;

    for (int t = tid; t < TILE_M; t += 512) {
        int p = p0 + t; if (p >= P) p = P - 1;
        smi[t] = mi[p]; sai[t] = ai[p];
        sdi[t] = di[p]; sgi[t] = gx[p]; ssi[t] = si[p];
    }
    if (tid >= 256 && tid < 256 + HP) {
        int h = tid - 256;
        s_b1[h] = (h < HD) ? b1[h] : 0.f;
        s_b2[h] = (h < HD) ? b2[h] : 0.f;
        s_w3[h] = (h < HD) ? W3[h] : 0.f;
    }
    __syncthreads();

    float acc[4][5][4];
    #pragma unroll
    for (int i = 0; i < 4; i++)
        #pragma unroll
        for (int j = 0; j < 5; j++)
            #pragma unroll
            for (int k = 0; k < 4; k++) acc[i][j][k] = 0.f;

    const int m = tid >> 1, q = tid & 1;   // row m (0..255), 64B half q

    uint4 iA[4];   // i-side prefetch only (16 regs)
    auto loadI = [&](int c) {
        const uint4* Ip = ((const uint4*)g_gib) + ((size_t)smi[m] * 128 + c * 8 + q * 4);
        iA[0] = Ip[0]; iA[1] = Ip[1]; iA[2] = Ip[2]; iA[3] = Ip[3];
    };
    auto storeA = [&](int c) {
        const uint4* Jp = ((const uint4*)g_gib) + ((size_t)sai[m] * 128 + c * 8 + q * 4);
        uint4 j0 = Jp[0], j1 = Jp[1], j2 = Jp[2], j3 = Jp[3];
        uint32_t asb = rbase + (uint32_t)((c & 1) * 32768) + (uint32_t)(m * 128 + q * 64);
        uint4 r;
        r.x = mul2(iA[0].x, j0.x); r.y = mul2(iA[0].y, j0.y); r.z = mul2(iA[0].z, j0.z); r.w = mul2(iA[0].w, j0.w);
        STS128(r.x, r.y, r.z, r.w, SWZ(asb));
        r.x = mul2(iA[1].x, j1.x); r.y = mul2(iA[1].y, j1.y); r.z = mul2(iA[1].z, j1.z); r.w = mul2(iA[1].w, j1.w);
        STS128(r.x, r.y, r.z, r.w, SWZ(asb + 16));
        r.x = mul2(iA[2].x, j2.x); r.y = mul2(iA[2].y, j2.y); r.z = mul2(iA[2].z, j2.z); r.w = mul2(iA[2].w, j2.w);
        STS128(r.x, r.y, r.z, r.w, SWZ(asb + 32));
        r.x = mul2(iA[3].x, j3.x); r.y = mul2(iA[3].y, j3.y); r.z = mul2(iA[3].z, j3.z); r.w = mul2(iA[3].w, j3.w);
        STS128(r.x, r.y, r.z, r.w, SWZ(asb + 48));
    };
    auto producePhi = [&]() {
        uint32_t asb = rbase + (uint32_t)(m * 128 + q * 64);   // chunk16 -> slot 0
        #pragma unroll
        for (int t4 = 0; t4 < 4; t4++) {
            uint32_t w[4];
            #pragma unroll
            for (int t = 0; t < 4; t++) {
                int kk = q * 32 + t4 * 8 + t * 2;
                float f0 = 0.f, f1 = 0.f;
                if (kk < 20)      f0 = de[sdi[m] * 20 + kk];
                else if (kk < 40) f0 = ge[sgi[m] * 20 + kk - 20];
                else if (kk < 60) f0 = se[ssi[m] * 20 + kk - 40];
                int k1 = kk + 1;
                if (k1 < 20)      f1 = de[sdi[m] * 20 + k1];
                else if (k1 < 40) f1 = ge[sgi[m] * 20 + k1 - 20];
                else if (k1 < 60) f1 = se[ssi[m] * 20 + k1 - 40];
                CVTB2(w[t], f0, f1);
            }
            STS128(w[0], w[1], w[2], w[3], SWZ(asb + t4 * 16));
        }
    };
    auto issueB = [&](int c) {
        uint32_t Bb = rbase + 65536u + (uint32_t)((c % 3) * 20480);
        const char* src = (const char*)(g_Bpack + c * 5120);
        #pragma unroll
        for (int t = 0; t < 3; t++) {
            int i = tid + t * 512;
            if (i < 1280) CPA16(Bb + (uint32_t)(i * 16), src + (size_t)i * 16);
        }
        CPC();
    };

    // ---- layer 1 pipeline: B 2 chunks ahead, 1 barrier/chunk ----
    issueB(0); issueB(1);
    loadI(0);
    storeA(0);
    for (int c = 0; c < NCHUNK; c++) {
        if (c + 1 < 16) loadI(c + 1);
        if (c < NCHUNK - 1) CPW1(); else CPW0();
        __syncthreads();
        if (c + 2 < NCHUNK) issueB(c + 2);
        mma_chunk40<4>(rbase + (uint32_t)((c & 1) * 32768),
                       rbase + 65536u + (uint32_t)((c % 3) * 20480),
                       4, mw * 64, nw * 40, lane, acc);
        if (c + 1 < NCHUNK) {
            if (c + 1 < 16) storeA(c + 1); else producePhi();
        }
    }
    __syncthreads();   // all MMA reads done before H/W2 overwrite

    // ---- W2^T cp.async (overlaps epilogue-1 gathers) ----
    {
        const char* src = (const char*)g_B2pack;
        #pragma unroll
        for (int t = 0; t < 8; t++) {
            int i = tid + t * 512;
            if (i < 3840) CPA16(W2b + (uint32_t)(i * 16), src + (size_t)i * 16);
        }
        CPC();
    }

    // ---- epilogue 1: +base, relu -> bf16 H tile in smem ----
    #pragma unroll
    for (int mt = 0; mt < 4; mt++)
        #pragma unroll
        for (int half = 0; half < 2; half++) {
            int r = mw * 64 + mt * 16 + (lane >> 2) + half * 8;
            const float* Ar = g_A + (size_t)smi[r] * HP;
            const float* Br = g_B + (size_t)sai[r] * HP;
            #pragma unroll
            for (int nt = 0; nt < 5; nt++) {
                int cc = nw * 40 + nt * 8 + (lane & 3) * 2;
                float2 av = *(const float2*)(Ar + cc);
                float2 bv = *(const float2*)(Br + cc);
                float2 b1v = *(const float2*)(s_b1 + cc);
                float x = acc[mt][nt][half * 2]     + av.x + bv.x + b1v.x;
                float y = acc[mt][nt][half * 2 + 1] + av.y + bv.y + b1v.y;
                x = fmaxf(x, 0.f); y = fmaxf(y, 0.f);
                uint32_t w; CVTB2(w, x, y);
                int ch = cc >> 6;
                uint32_t off = Hb + (uint32_t)(ch * 32768) +
                               SWZ((uint32_t)(r * 128 + (cc & 63) * 2));
                STS32(off, w);
            }
        }
    CPW0();
    __syncthreads();

    // ---- layer 2 ----
    #pragma unroll
    for (int i = 0; i < 4; i++)
        #pragma unroll
        for (int j = 0; j < 5; j++)
            #pragma unroll
            for (int k = 0; k < 4; k++) acc[i][j][k] = 0.f;
    #pragma unroll
    for (int ch = 0; ch < 3; ch++)
        mma_chunk40<4>(Hb + ch * 32768, W2b + ch * 20480, (ch == 2) ? 2 : 4,
                       mw * 64, nw * 40, lane, acc);

    // ---- epilogue 2: relu(+b2) . W3 -> reduce -> scores ----
    #pragma unroll
    for (int mt = 0; mt < 4; mt++)
        #pragma unroll
        for (int half = 0; half < 2; half++) {
            float part = 0.f;
            #pragma unroll
            for (int nt = 0; nt < 5; nt++) {
                int cc = nw * 40 + nt * 8 + (lane & 3) * 2;
                float h0 = fmaxf(acc[mt][nt][half * 2]     + s_b2[cc],     0.f);
                float h1 = fmaxf(acc[mt][nt][half * 2 + 1] + s_b2[cc + 1], 0.f);
                part += h0 * s_w3[cc] + h1 * s_w3[cc + 1];
            }
            part += __shfl_xor_sync(0xffffffffu, part, 1);
            part += __shfl_xor_sync(0xffffffffu, part, 2);
            if ((lane & 3) == 0) {
                int r = mw * 64 + mt * 16 + (lane >> 2) + half * 8;
                sred[r][nw] = part;
            }
        }
    __syncthreads();
    for (int t = tid; t < TILE_M; t += 512) {
        int p = p0 + t;
        if (p < P) {
            float s = sred[t][0] + sred[t][1] + sred[t][2] + sred[t][3]
                    + b3[0] + ms[smi[t]] + ms[sai[t]];
            g_scores[p] = s;
        }
    }
}

// ============================================================
__global__ __launch_bounds__(128) void k_softmax(const int* __restrict__ lengths,
                                                 float* __restrict__ out)
{
    int g = blockIdx.x;
    int tid = threadIdx.x;
    int len = lengths[g];
    int st = g_starts[g];
    __shared__ float sm[4], ss[4];

    float v = (tid < len) ? g_scores[st + tid] : -3.4e38f;
    float mx = v;
    #pragma unroll
    for (int o = 16; o > 0; o >>= 1) mx = fmaxf(mx, __shfl_xor_sync(0xffffffffu, mx, o));
    if ((tid & 31) == 0) sm[tid >> 5] = mx;
    __syncthreads();
    mx = fmaxf(fmaxf(sm[0], sm[1]), fmaxf(sm[2], sm[3]));
    mx = fmaxf(mx, 0.f);

    float e = (tid < len) ? expf(v - mx) : 0.f;
    float s = e;
    #pragma unroll
    for (int o = 16; o > 0; o >>= 1) s += __shfl_xor_sync(0xffffffffu, s, o);
    if ((tid & 31) == 0) ss[tid >> 5] = s;
    __syncthreads();

    float epse = expf(-mx);
    float denom = ss[0] + ss[1] + ss[2] + ss[3] + epse;
    float* row = out + (size_t)(g + 1) * GRIDW;
    if (tid < len) row[tid] = e / denom;
    if (tid == 0)  row[len] = epse / denom;
}

// ============================================================
extern "C" void kernel_launch(void* const* d_in, const int* in_sizes, int n_in,
                              void* d_out, int out_size)
{
    const float* gi   = (const float*)d_in[0];
    const float* ms   = (const float*)d_in[1];
    const float* de   = (const float*)d_in[2];
    const float* ge   = (const float*)d_in[3];
    const float* se   = (const float*)d_in[4];
    const float* W1   = (const float*)d_in[5];
    const float* b1   = (const float*)d_in[6];
    const float* W2   = (const float*)d_in[7];
    const float* b2   = (const float*)d_in[8];
    const float* W3   = (const float*)d_in[9];
    const float* b3   = (const float*)d_in[10];
    const int*   mi   = (const int*)d_in[11];
    const int*   ai   = (const int*)d_in[12];
    const int*   di   = (const int*)d_in[13];
    const int*   gidx = (const int*)d_in[14];
    const int*   si   = (const int*)d_in[15];
    const int*   lens = (const int*)d_in[16];
    const int*   segs = (const int*)d_in[17];
    const int*   offs = (const int*)d_in[18];
    float* out = (float*)d_out;

    const int P = in_sizes[11];
    const int M = in_sizes[16];
    const int NSPAN = in_sizes[0] / GDIM;   // 4096

    const int DS_PRE   = 114688 + 1024;
    const int DS_FUSED = 159744 + 1024;
    static int configured = 0;
    if (!configured) {
        cudaFuncSetAttribute(k_pre,   cudaFuncAttributeMaxDynamicSharedMemorySize, DS_PRE);
        cudaFuncSetAttribute(k_fused, cudaFuncAttributeMaxDynamicSharedMemorySize, DS_FUSED);
        configured = 1;
    }

    long long prep_total = (long long)NSPAN * 512 + (2 * 16 + NCHUNK + 3) * 5120
                         + out_size + P;
    k_prep<<<(int)((prep_total + 255) / 256), 256>>>(gi, W1, W2, offs, segs, out,
                                                     NSPAN, P, out_size);

    k_pre<<<dim3(NSPAN / 64, 2), 512, DS_PRE>>>();

    int NT = (P + TILE_M - 1) / TILE_M;
    k_fused<<<NT, 512, DS_FUSED>>>(b1, b2, W3, b3, ms, de, ge, se,
                                   mi, ai, di, gidx, si, P);

    k_softmax<<<M, 128>>>(lens, out);
}

// round 8
// speedup vs baseline: 1.2565x; 1.2565x over previous
#include <cuda_runtime.h>
#include <cuda_bf16.h>
#include <cstdint>

#define HD 150
#define HP 160
#define GDIM 1000
#define GRIDW 129
#define NCHUNK 17

typedef unsigned long long ull;

// ---------------- helpers ----------------
__device__ __forceinline__ uint32_t smem_u32(const void* p){
    uint32_t a; asm("{ .reg .u64 t; cvta.to.shared.u64 t, %1; cvt.u32.u64 %0, t; }" : "=r"(a) : "l"(p));
    return a;
}
__device__ __forceinline__ uint32_t mul2(uint32_t a, uint32_t b){
    uint32_t r; asm("mul.bf16x2 %0,%1,%2;" : "=r"(r) : "r"(a), "r"(b)); return r;
}
#define CVTB2(res,a,b) asm("cvt.rn.satfinite.bf16x2.f32 %0, %1, %2;" : "=r"(res) : "f"(b), "f"(a))
#define STS128(r0,r1,r2,r3,addr) asm volatile("st.shared.v4.b32 [%0], {%1,%2,%3,%4};" :: "r"(addr), "r"(r0), "r"(r1), "r"(r2), "r"(r3) : "memory")
#define STS32(addr,v) asm volatile("st.shared.b32 [%0], %1;" :: "r"(addr), "r"(v) : "memory")
#define SWZ(a) ((a) ^ (((a)>>3)&0x70))

__device__ __forceinline__ float2 unpack_bf2(uint32_t v){
    float2 r;
    r.x = __uint_as_float(v << 16);
    r.y = __uint_as_float(v & 0xffff0000u);
    return r;
}

#define CPA16(dst,src) asm volatile("cp.async.cg.shared.global [%0], [%1], 16;" :: "r"((uint32_t)(dst)), "l"(src) : "memory")
#define CPC() asm volatile("cp.async.commit_group;" ::: "memory")
#define CPW0() asm volatile("cp.async.wait_group 0;" ::: "memory")
#define CPW1() asm volatile("cp.async.wait_group 1;" ::: "memory")
#define CPW2() asm volatile("cp.async.wait_group 2;" ::: "memory")

#define LDSM4(r0,r1,r2,r3,addr) \
    asm volatile("ldmatrix.sync.aligned.m8n8.x4.shared.b16 {%0,%1,%2,%3}, [%4];" \
        : "=r"(r0),"=r"(r1),"=r"(r2),"=r"(r3) : "r"(addr))
#define LDSM2(r0,r1,addr) \
    asm volatile("ldmatrix.sync.aligned.m8n8.x2.shared.b16 {%0,%1}, [%2];" \
        : "=r"(r0),"=r"(r1) : "r"(addr))

#define MMA(d,a,b) \
    asm volatile("mma.sync.aligned.m16n8k16.row.col.f32.bf16.bf16.f32 " \
        "{%0,%1,%2,%3},{%4,%5,%6,%7},{%8,%9},{%0,%1,%2,%3};" \
        : "+f"((d)[0]),"+f"((d)[1]),"+f"((d)[2]),"+f"((d)[3]) \
        : "r"((a)[0]),"r"((a)[1]),"r"((a)[2]),"r"((a)[3]),"r"((b)[0]),"r"((b)[1]))

// ---------------- scratch ----------------
__device__ uint32_t g_gib[4096 * 512];          // gi as bf16x2, K padded to 1024
__device__ uint32_t g_ABpack[2 * 16 * 5120];    // W1a^T, W1b^T pre-swizzled chunks
__device__ uint32_t g_Bpack[NCHUNK * 5120];     // W1c^T / W1d^T chunks
__device__ uint32_t g_B2pack[3 * 5120];         // W2^T chunks
__device__ uint32_t g_A[4096 * 80];             // (gi@W1a + b1) as bf16x2
__device__ uint32_t g_B[4096 * 80];             // (gi@W1b) as bf16x2
__device__ float g_scores[132096];
__device__ int   g_starts[2048];

// ============================================================
// warp MMA consumer, N40: per k16 -> 2x LDSM4 + 1x LDSM2 for B
// ============================================================
template<int MT>
__device__ __forceinline__ void mma_chunk40(uint32_t Ab, uint32_t Bb, int nk16,
                                            int mrow0, int nrow0, int lane,
                                            float (&acc)[MT][5][4])
{
    const int a_row = mrow0 + ((lane>>3)&1)*8 + (lane&7);
    const int a_cb  = (lane>>4)*16;
    const int b_row = nrow0 + ((lane>>4)&1)*8 + (lane&7);
    const int b_cb  = ((lane>>3)&1)*16;
    const int b2_row = nrow0 + 32 + (lane&7);
    const int b2_cb  = ((lane>>3)&1)*16;
    #pragma unroll
    for (int k16 = 0; k16 < nk16; k16++) {
        const int kb = k16 * 32;
        uint32_t a[MT][4];
        #pragma unroll
        for (int mt = 0; mt < MT; mt++) {
            uint32_t ad = Ab + SWZ((uint32_t)((a_row + mt*16)*128 + kb + a_cb));
            LDSM4(a[mt][0], a[mt][1], a[mt][2], a[mt][3], ad);
        }
        uint32_t b[5][2];
        #pragma unroll
        for (int g = 0; g < 2; g++) {
            uint32_t bd = Bb + SWZ((uint32_t)((b_row + g*16)*128 + kb + b_cb));
            uint32_t r0, r1, r2, r3;
            LDSM4(r0, r1, r2, r3, bd);
            b[2*g][0] = r0; b[2*g][1] = r1; b[2*g+1][0] = r2; b[2*g+1][1] = r3;
        }
        {
            uint32_t bd = Bb + SWZ((uint32_t)(b2_row*128 + kb + b2_cb));
            LDSM2(b[4][0], b[4][1], bd);
        }
        #pragma unroll
        for (int mt = 0; mt < MT; mt++)
            #pragma unroll
            for (int nt = 0; nt < 5; nt++)
                MMA(acc[mt][nt], a[mt], b[nt]);
    }
}

// ============================================================
// prep (fused with fill + starts)
// ============================================================
__global__ void k_prep(const float* __restrict__ gi, const float* __restrict__ W1,
                       const float* __restrict__ W2,
                       const int* __restrict__ offs, const int* __restrict__ segs,
                       float* __restrict__ out, int NSPAN, int P, int out_total)
{
    long long idx = (long long)blockIdx.x * 256 + threadIdx.x;
    const long long NG  = (long long)NSPAN * 512;
    const long long AB  = NG + 2 * 16 * 5120;
    const long long BP  = AB + NCHUNK * 5120;
    const long long B2E = BP + 3 * 5120;
    const long long FE  = B2E + out_total;
    const long long SE  = FE + P;
    if (idx < NG) {
        int n = (int)(idx >> 9), kw = (int)(idx & 511);
        int c0 = kw * 2;
        float a = (c0     < GDIM) ? gi[(size_t)n * GDIM + c0]     : 0.f;
        float b = (c0 + 1 < GDIM) ? gi[(size_t)n * GDIM + c0 + 1] : 0.f;
        uint32_t w; CVTB2(w, a, b);
        g_gib[idx] = w;
    } else if (idx < AB) {
        int t = (int)(idx - NG);
        int sel = t / (16 * 5120); int rem = t - sel * 16 * 5120;
        int c = rem / 5120, r = rem % 5120;
        int n = r >> 5, kk = (r & 31) * 2;
        int kg = c * 64 + kk;
        float v0 = 0.f, v1 = 0.f;
        if (n < HD) {
            if (kg     < GDIM) v0 = W1[(size_t)(sel * GDIM + kg)     * HD + n];
            if (kg + 1 < GDIM) v1 = W1[(size_t)(sel * GDIM + kg + 1) * HD + n];
        }
        uint32_t w; CVTB2(w, v0, v1);
        uint32_t off = (uint32_t)(n * 128 + kk * 2);
        g_ABpack[(sel * 16 + c) * 5120 + (SWZ(off) >> 2)] = w;
    } else if (idx < BP) {
        int t = (int)(idx - AB);
        int c = t / 5120, r = t % 5120;
        int n = r >> 5, kk = (r & 31) * 2;
        float v0 = 0.f, v1 = 0.f;
        if (n < HD) {
            if (c < 16) {
                int kg = c * 64 + kk;
                if (kg     < GDIM) v0 = W1[(size_t)(2000 + kg)     * HD + n];
                if (kg + 1 < GDIM) v1 = W1[(size_t)(2001 + kg)     * HD + n];
            } else {
                if (kk     < 60) v0 = W1[(size_t)(3000 + kk)     * HD + n];
                if (kk + 1 < 60) v1 = W1[(size_t)(3001 + kk)     * HD + n];
            }
        }
        uint32_t w; CVTB2(w, v0, v1);
        uint32_t off = (uint32_t)(n * 128 + kk * 2);
        g_Bpack[c * 5120 + (SWZ(off) >> 2)] = w;
    } else if (idx < B2E) {
        int t = (int)(idx - BP);
        int c = t / 5120, r = t % 5120;
        int n = r >> 5, kk = (r & 31) * 2;
        int kg = c * 64 + kk;
        float v0 = 0.f, v1 = 0.f;
        if (n < HD) {
            if (kg     < HD) v0 = W2[(size_t)kg       * HD + n];
            if (kg + 1 < HD) v1 = W2[(size_t)(kg + 1) * HD + n];
        }
        uint32_t w; CVTB2(w, v0, v1);
        uint32_t off = (uint32_t)(n * 128 + kk * 2);
        g_B2pack[c * 5120 + (SWZ(off) >> 2)] = w;
    } else if (idx < FE) {
        long long i = idx - B2E;
        out[i] = (i == 0) ? 1.0f : 1000.0f;
    } else if (idx < SE) {
        int p = (int)(idx - FE);
        if (offs[p] == 0) g_starts[segs[p]] = p;
    }
}

// ============================================================
// k_pre: g_A = (gi @ W1a) + b1, g_B = gi @ W1b   (bf16x2 output)
// 4-deep cp.async ring, one barrier per chunk
// grid (NSPAN/64, 2), 512 threads; warp grid 4x4: M16 x N40
// ============================================================
__global__ __launch_bounds__(512) void k_pre(const float* __restrict__ b1)
{
    extern __shared__ char dsm[];
    const int tid = threadIdx.x;
    const int lane = tid & 31;
    const int wid = tid >> 5;
    const int mw = wid & 3, nw = wid >> 2;
    const int n0 = blockIdx.x * 64;
    const int sel = blockIdx.y;

    uint32_t rbase = (smem_u32(dsm) + 1023u) & ~1023u;
    const char* Bsrc = (const char*)(g_ABpack + sel * 16 * 5120);

    float acc[1][5][4];
    #pragma unroll
    for (int j = 0; j < 5; j++)
        #pragma unroll
        for (int k = 0; k < 4; k++) acc[0][j][k] = 0.f;

    auto issue = [&](int c) {
        int s = c & 3;
        uint32_t Ab = rbase + (uint32_t)(s * 8192);
        uint32_t Bb = rbase + 32768u + (uint32_t)(s * 20480);
        {
            int row = tid >> 3, seg = tid & 7;
            const char* src = (const char*)g_gib + ((size_t)(n0 + row) * 2048 + c * 128 + seg * 16);
            CPA16(Ab + SWZ((uint32_t)(row * 128 + seg * 16)), src);
        }
        #pragma unroll
        for (int t = 0; t < 3; t++) {
            int j = tid + t * 512;
            if (j < 1280) CPA16(Bb + (uint32_t)(j * 16), Bsrc + (size_t)c * 20480 + j * 16);
        }
        CPC();
    };

    issue(0); issue(1); issue(2);
    for (int c = 0; c < 16; c++) {
        if (c <= 13) CPW2(); else if (c == 14) CPW1(); else CPW0();
        __syncthreads();
        if (c + 3 < 16) issue(c + 3);
        int s = c & 3;
        mma_chunk40<1>(rbase + (uint32_t)(s * 8192),
                       rbase + 32768u + (uint32_t)(s * 20480),
                       4, mw * 16, nw * 40, lane, acc);
    }

    uint32_t* dst = sel ? g_B : g_A;
    #pragma unroll
    for (int half = 0; half < 2; half++) {
        int row = n0 + mw * 16 + (lane >> 2) + half * 8;
        #pragma unroll
        for (int nt = 0; nt < 5; nt++) {
            int cc = nw * 40 + nt * 8 + (lane & 3) * 2;
            float x = acc[0][nt][half * 2];
            float y = acc[0][nt][half * 2 + 1];
            if (!sel) { x += b1[cc]; y += b1[cc + 1]; }   // fold b1; cols>=HD get b1 pad? cc<160, b1 only HD valid
            uint32_t w; CVTB2(w, x, y);
            dst[(size_t)row * 80 + (cc >> 1)] = w;
        }
    }
}

// ============================================================
// fused pair kernel: layer1 HMMA + relu + layer2 HMMA + score
// 4-deep B ring, one barrier per chunk, 512 threads, 4x4 warps M32xN40
// ============================================================
__global__ __launch_bounds__(512) void k_fused(
    const float* __restrict__ b2,
    const float* __restrict__ W3, const float* __restrict__ b3,
    const float* __restrict__ ms,
    const float* __restrict__ de, const float* __restrict__ ge, const float* __restrict__ se,
    const int* __restrict__ mi, const int* __restrict__ ai,
    const int* __restrict__ di, const int* __restrict__ gx, const int* __restrict__ si,
    int P)
{
    extern __shared__ char dsm[];
    __shared__ int smi[128], sai[128], sdi[128], sgi[128], ssi[128];
    __shared__ __align__(16) float s_b2[HP], s_w3[HP];
    __shared__ float sred[128][4];

    const int tid = threadIdx.x;
    const int lane = tid & 31;
    const int wid = tid >> 5;
    const int mw = wid & 3, nw = wid >> 2;
    const int p0 = blockIdx.x * 128;

    uint32_t rbase = (smem_u32(dsm) + 1023u) & ~1023u;
    const uint32_t Hb  = rbase;
    const uint32_t W2b = rbase + 53248u;

    if (tid < 128) {
        int p = p0 + tid; if (p >= P) p = P - 1;
        smi[tid] = mi[p]; sai[tid] = ai[p];
        sdi[tid] = di[p]; sgi[tid] = gx[p]; ssi[tid] = si[p];
    }
    if (tid >= 256 && tid < 256 + HP) {
        int h = tid - 256;
        s_b2[h] = (h < HD) ? b2[h] : 0.f;
        s_w3[h] = (h < HD) ? W3[h] : 0.f;
    }
    __syncthreads();

    float acc[2][5][4];
    #pragma unroll
    for (int i = 0; i < 2; i++)
        #pragma unroll
        for (int j = 0; j < 5; j++)
            #pragma unroll
            for (int k = 0; k < 4; k++) acc[i][j][k] = 0.f;

    const int m = tid >> 2, q = tid & 3;

    uint4 iA[2], jA[2];
    auto loadA = [&](int c) {
        const uint4* Ip = ((const uint4*)g_gib) + ((size_t)smi[m] * 128 + c * 8 + q * 2);
        const uint4* Jp = ((const uint4*)g_gib) + ((size_t)sai[m] * 128 + c * 8 + q * 2);
        iA[0] = Ip[0]; iA[1] = Ip[1];
        jA[0] = Jp[0]; jA[1] = Jp[1];
    };
    auto storeA = [&](int c) {
        uint32_t asb = rbase + (uint32_t)((c & 1) * 16384) + (uint32_t)(m * 128 + q * 32);
        #pragma unroll
        for (int t = 0; t < 2; t++) {
            uint4 r;
            r.x = mul2(iA[t].x, jA[t].x); r.y = mul2(iA[t].y, jA[t].y);
            r.z = mul2(iA[t].z, jA[t].z); r.w = mul2(iA[t].w, jA[t].w);
            STS128(r.x, r.y, r.z, r.w, SWZ(asb + t * 16));
        }
    };
    auto producePhi = [&]() {
        uint32_t asb = rbase + (uint32_t)(m * 128 + q * 32);   // chunk16 -> buf0
        uint32_t w[8];
        #pragma unroll
        for (int t = 0; t < 8; t++) {
            int kk = q * 16 + t * 2;
            float f0 = 0.f, f1 = 0.f;
            if (kk < 20)      f0 = de[sdi[m] * 20 + kk];
            else if (kk < 40) f0 = ge[sgi[m] * 20 + kk - 20];
            else if (kk < 60) f0 = se[ssi[m] * 20 + kk - 40];
            int k1 = kk + 1;
            if (k1 < 20)      f1 = de[sdi[m] * 20 + k1];
            else if (k1 < 40) f1 = ge[sgi[m] * 20 + k1 - 20];
            else if (k1 < 60) f1 = se[ssi[m] * 20 + k1 - 40];
            CVTB2(w[t], f0, f1);
        }
        STS128(w[0], w[1], w[2], w[3], SWZ(asb));
        STS128(w[4], w[5], w[6], w[7], SWZ(asb + 16));
    };
    auto issueB = [&](int c) {
        uint32_t Bb = rbase + 32768u + (uint32_t)((c & 3) * 20480);
        const char* src = (const char*)(g_Bpack + c * 5120);
        #pragma unroll
        for (int t = 0; t < 3; t++) {
            int i = tid + t * 512;
            if (i < 1280) CPA16(Bb + (uint32_t)(i * 16), src + (size_t)i * 16);
        }
        CPC();
    };

    // ---- layer 1 pipeline: B 3 chunks ahead, 1 barrier/chunk ----
    issueB(0); issueB(1); issueB(2);
    loadA(0);
    storeA(0);
    for (int c = 0; c < NCHUNK; c++) {
        if (c + 1 < 16) loadA(c + 1);
        if (c < 15) CPW2(); else if (c == 15) CPW1(); else CPW0();
        __syncthreads();
        if (c + 3 < NCHUNK) issueB(c + 3);
        int s = c & 3;
        mma_chunk40<2>(rbase + (uint32_t)((c & 1) * 16384),
                       rbase + 32768u + (uint32_t)(s * 20480),
                       4, mw * 32, nw * 40, lane, acc);
        if (c + 1 < NCHUNK) {
            if (c + 1 < 16) storeA(c + 1); else producePhi();
        }
    }
    __syncthreads();   // all MMA reads done before H/W2 overwrite A/B regions

    // ---- W2^T cp.async (into dead B-ring slots 1..3) ----
    {
        const char* src = (const char*)g_B2pack;
        #pragma unroll
        for (int t = 0; t < 8; t++) {
            int i = tid + t * 512;
            if (i < 3840) CPA16(W2b + (uint32_t)(i * 16), src + (size_t)i * 16);
        }
        CPC();
    }

    // ---- epilogue 1: +(A[mi]+b1)+(B[ai]), relu -> bf16 H tile in smem ----
    #pragma unroll
    for (int mt = 0; mt < 2; mt++)
        #pragma unroll
        for (int half = 0; half < 2; half++) {
            int r = mw * 32 + mt * 16 + (lane >> 2) + half * 8;
            const uint32_t* Ar = g_A + (size_t)smi[r] * 80;
            const uint32_t* Br = g_B + (size_t)sai[r] * 80;
            #pragma unroll
            for (int nt = 0; nt < 5; nt++) {
                int cc = nw * 40 + nt * 8 + (lane & 3) * 2;
                float2 av = unpack_bf2(Ar[cc >> 1]);
                float2 bv = unpack_bf2(Br[cc >> 1]);
                float x = acc[mt][nt][half * 2]     + av.x + bv.x;
                float y = acc[mt][nt][half * 2 + 1] + av.y + bv.y;
                x = fmaxf(x, 0.f); y = fmaxf(y, 0.f);
                uint32_t w; CVTB2(w, x, y);
                int ch = cc >> 6;
                uint32_t off = Hb + (uint32_t)(ch * 16384) +
                               SWZ((uint32_t)(r * 128 + (cc & 63) * 2));
                STS32(off, w);
            }
        }
    CPW0();
    __syncthreads();

    // ---- layer 2 ----
    #pragma unroll
    for (int i = 0; i < 2; i++)
        #pragma unroll
        for (int j = 0; j < 5; j++)
            #pragma unroll
            for (int k = 0; k < 4; k++) acc[i][j][k] = 0.f;
    #pragma unroll
    for (int ch = 0; ch < 3; ch++)
        mma_chunk40<2>(Hb + ch * 16384, W2b + ch * 20480, (ch == 2) ? 2 : 4,
                       mw * 32, nw * 40, lane, acc);

    // ---- epilogue 2: relu(+b2) . W3 -> reduce -> scores ----
    #pragma unroll
    for (int mt = 0; mt < 2; mt++)
        #pragma unroll
        for (int half = 0; half < 2; half++) {
            float part = 0.f;
            #pragma unroll
            for (int nt = 0; nt < 5; nt++) {
                int cc = nw * 40 + nt * 8 + (lane & 3) * 2;
                float h0 = fmaxf(acc[mt][nt][half * 2]     + s_b2[cc],     0.f);
                float h1 = fmaxf(acc[mt][nt][half * 2 + 1] + s_b2[cc + 1], 0.f);
                part += h0 * s_w3[cc] + h1 * s_w3[cc + 1];
            }
            part += __shfl_xor_sync(0xffffffffu, part, 1);
            part += __shfl_xor_sync(0xffffffffu, part, 2);
            if ((lane & 3) == 0) {
                int r = mw * 32 + mt * 16 + (lane >> 2) + half * 8;
                sred[r][nw] = part;
            }
        }
    __syncthreads();
    if (tid < 128) {
        int p = p0 + tid;
        if (p < P) {
            float s = sred[tid][0] + sred[tid][1] + sred[tid][2] + sred[tid][3]
                    + b3[0] + ms[smi[tid]] + ms[sai[tid]];
            g_scores[p] = s;
        }
    }
}

// ============================================================
__global__ __launch_bounds__(128) void k_softmax(const int* __restrict__ lengths,
                                                 float* __restrict__ out)
{
    int g = blockIdx.x;
    int tid = threadIdx.x;
    int len = lengths[g];
    int st = g_starts[g];
    __shared__ float sm[4], ss[4];

    float v = (tid < len) ? g_scores[st + tid] : -3.4e38f;
    float mx = v;
    #pragma unroll
    for (int o = 16; o > 0; o >>= 1) mx = fmaxf(mx, __shfl_xor_sync(0xffffffffu, mx, o));
    if ((tid & 31) == 0) sm[tid >> 5] = mx;
    __syncthreads();
    mx = fmaxf(fmaxf(sm[0], sm[1]), fmaxf(sm[2], sm[3]));
    mx = fmaxf(mx, 0.f);

    float e = (tid < len) ? expf(v - mx) : 0.f;
    float s = e;
    #pragma unroll
    for (int o = 16; o > 0; o >>= 1) s += __shfl_xor_sync(0xffffffffu, s, o);
    if ((tid & 31) == 0) ss[tid >> 5] = s;
    __syncthreads();

    float epse = expf(-mx);
    float denom = ss[0] + ss[1] + ss[2] + ss[3] + epse;
    float* row = out + (size_t)(g + 1) * GRIDW;
    if (tid < len) row[tid] = e / denom;
    if (tid == 0)  row[len] = epse / denom;
}

// ============================================================
extern "C" void kernel_launch(void* const* d_in, const int* in_sizes, int n_in,
                              void* d_out, int out_size)
{
    const float* gi   = (const float*)d_in[0];
    const float* ms   = (const float*)d_in[1];
    const float* de   = (const float*)d_in[2];
    const float* ge   = (const float*)d_in[3];
    const float* se   = (const float*)d_in[4];
    const float* W1   = (const float*)d_in[5];
    const float* b1   = (const float*)d_in[6];
    const float* W2   = (const float*)d_in[7];
    const float* b2   = (const float*)d_in[8];
    const float* W3   = (const float*)d_in[9];
    const float* b3   = (const float*)d_in[10];
    const int*   mi   = (const int*)d_in[11];
    const int*   ai   = (const int*)d_in[12];
    const int*   di   = (const int*)d_in[13];
    const int*   gidx = (const int*)d_in[14];
    const int*   si   = (const int*)d_in[15];
    const int*   lens = (const int*)d_in[16];
    const int*   segs = (const int*)d_in[17];
    const int*   offs = (const int*)d_in[18];
    float* out = (float*)d_out;

    const int P = in_sizes[11];
    const int M = in_sizes[16];
    const int NSPAN = in_sizes[0] / GDIM;   // 4096

    const int DS = 114688 + 1024;
    static int configured = 0;
    if (!configured) {
        cudaFuncSetAttribute(k_pre,   cudaFuncAttributeMaxDynamicSharedMemorySize, DS);
        cudaFuncSetAttribute(k_fused, cudaFuncAttributeMaxDynamicSharedMemorySize, DS);
        configured = 1;
    }

    long long prep_total = (long long)NSPAN * 512 + (2 * 16 + NCHUNK + 3) * 5120
                         + out_size + P;
    k_prep<<<(int)((prep_total + 255) / 256), 256>>>(gi, W1, W2, offs, segs, out,
                                                     NSPAN, P, out_size);

    k_pre<<<dim3(NSPAN / 64, 2), 512, DS>>>(b1);

    int NT = (P + 127) / 128;
    k_fused<<<NT, 512, DS>>>(b2, W3, b3, ms, de, ge, se,
                             mi, ai, di, gidx, si, P);

    k_softmax<<<M, 128>>>(lens, out);
}